// round 4
// baseline (speedup 1.0000x reference)
#include <cuda_runtime.h>

#define HID 64
#define G3  192     // 3*H
#define BB  512
#define TT  1024
#define GEMM_ROWS 128

// ---------------- scratch (device globals; no allocations) ----------------
__device__ float g_xg[(size_t)BB * TT * G3];   // 402 MB
__device__ float g_hA[(size_t)BB * TT * HID];  // 134 MB
__device__ float g_hB[(size_t)BB * TT * HID];  // 134 MB

typedef unsigned long long u64;

__device__ __forceinline__ void ffma2(u64& acc, u64 a, u64 b) {
    asm("fma.rn.f32x2 %0, %1, %2, %0;" : "+l"(acc) : "l"(a), "l"(b));
}
__device__ __forceinline__ float hsum2(u64 v) {
    float lo, hi;
    asm("mov.b64 {%0, %1}, %2;" : "=f"(lo), "=f"(hi) : "l"(v));
    return lo + hi;
}

__device__ __forceinline__ float fsig(float x) {
    return __fdividef(1.0f, 1.0f + __expf(-x));
}
__device__ __forceinline__ float ftanh_fast(float x) {
    float e = __expf(-2.0f * x);
    return __fdividef(1.0f - e, 1.0f + e);
}

// ---------------- layer-0 input pre-activations (K=5, memory bound) -------
__global__ __launch_bounds__(192) void xg0_kernel(
    const float* __restrict__ x, const float* __restrict__ w,
    const float* __restrict__ b)
{
    __shared__ float ws[G3 * 5];
    __shared__ float bs[G3];
    __shared__ float xs[8][5];
    int g = threadIdx.x;                  // 0..191
    for (int i = g; i < G3 * 5; i += 192) ws[i] = w[i];
    if (g < G3) bs[g] = b[g];
    size_t row0 = (size_t)blockIdx.x * 8;
    if (g < 40) xs[g / 5][g % 5] = x[row0 * 5 + g];
    __syncthreads();
#pragma unroll
    for (int r = 0; r < 8; r++) {
        float acc = bs[g];
#pragma unroll
        for (int i = 0; i < 5; i++) acc += xs[r][i] * ws[g * 5 + i];
        g_xg[(row0 + r) * G3 + g] = acc;
    }
}

// ---------------- xg GEMM for layers 1..4: [BT,64]x[64,192]+b -------------
// 2 output cols per thread (g, g+96), rows split in halves across warps.
// ffma2:LDS ratio 4:1 so LSU no longer co-saturates with the FMA pipe.
__global__ void __launch_bounds__(192, 2) xg_gemm_kernel(
    int insel, const float* __restrict__ w, const float* __restrict__ bias)
{
    const float* __restrict__ hin = insel ? g_hB : g_hA;
    __shared__ __align__(16) float hs[GEMM_ROWS][HID];  // 32 KB
    int t  = threadIdx.x;
    int g  = t % 96;                      // column-pair base
    int rh = t / 96;                      // row half (warps 0-2: 0, 3-5: 1)

    u64 w0[32], w1[32];
    const ulonglong2* p0 = (const ulonglong2*)&w[(size_t)g * HID];
    const ulonglong2* p1 = (const ulonglong2*)&w[(size_t)(g + 96) * HID];
#pragma unroll
    for (int q = 0; q < 16; q++) {
        ulonglong2 a = p0[q]; w0[2 * q] = a.x; w0[2 * q + 1] = a.y;
        ulonglong2 c = p1[q]; w1[2 * q] = c.x; w1[2 * q + 1] = c.y;
    }
    float b0 = bias[g], b1 = bias[g + 96];

    size_t row0 = (size_t)blockIdx.x * GEMM_ROWS;
    const float4* src = (const float4*)&hin[row0 * HID];
    float4* dst = (float4*)&hs[0][0];
    for (int i = t; i < GEMM_ROWS * HID / 4; i += 192) dst[i] = src[i];
    __syncthreads();

    float* outp = &g_xg[(row0 + (size_t)rh * 64) * G3];
#pragma unroll 1
    for (int r = 0; r < 64; r++) {
        u64 a0 = 0, a1 = 0, c0 = 0, c1 = 0;
        const ulonglong2* hrow = (const ulonglong2*)&hs[rh * 64 + r][0];
#pragma unroll
        for (int q = 0; q < 16; q++) {
            ulonglong2 hv = hrow[q];            // LDS.128 broadcast per warp
            ffma2(a0, w0[2 * q], hv.x);
            ffma2(a1, w0[2 * q + 1], hv.y);
            ffma2(c0, w1[2 * q], hv.x);
            ffma2(c1, w1[2 * q + 1], hv.y);
        }
        outp[r * G3 + g]      = b0 + hsum2(a0) + hsum2(a1);
        outp[r * G3 + g + 96] = b1 + hsum2(c0) + hsum2(c1);
    }
}

// ---------------- recurrence: thread = (hidden unit, K-half) --------------
// 512 thr = 4 groups x (64 units x 2 K-halves). Weight regs halved (96)
// so the whole CTA fits the RF at 128 regs -> 16 warps/SM, 4 chains/SMSP.
// shfl.xor(1) combines K-halves; one 128-thread named barrier per step.
template<bool WRITE_ALL>
__global__ void __launch_bounds__(512, 1) rec_kernel(
    const float* __restrict__ whh, const float* __restrict__ bhh, int outsel)
{
    float* __restrict__ hout = outsel ? g_hB : g_hA;
    __shared__ __align__(16) float hbuf[2][4][HID];

    int tid  = threadIdx.x;
    int grp  = tid >> 7;                  // 0..3 batch row within CTA
    int gt   = tid & 127;
    int j    = gt >> 1;                   // hidden unit
    int half = gt & 1;                    // K half
    int b    = blockIdx.x * 4 + grp;
    int barid = grp + 1;

    // weight rows j (r), 64+j (z), 128+j (n); k in [half*32, half*32+32)
    u64 wr[16], wz[16], wn[16];
    {
        const float* base = whh + half * 32;
        const ulonglong2* rr = (const ulonglong2*)(base + (size_t)j * HID);
        const ulonglong2* rz = (const ulonglong2*)(base + (size_t)(HID + j) * HID);
        const ulonglong2* rn = (const ulonglong2*)(base + (size_t)(2 * HID + j) * HID);
#pragma unroll
        for (int q = 0; q < 8; q++) {
            ulonglong2 a = rr[q]; wr[2 * q] = a.x; wr[2 * q + 1] = a.y;
            ulonglong2 c = rz[q]; wz[2 * q] = c.x; wz[2 * q + 1] = c.y;
            ulonglong2 d = rn[q]; wn[2 * q] = d.x; wn[2 * q + 1] = d.y;
        }
    }
    float br = bhh[j], bz = bhh[HID + j], bn = bhh[2 * HID + j];

    if (half == 0) hbuf[0][grp][j] = 0.0f;
    float hprev = 0.0f;

    const float* xgp = g_xg + (size_t)b * TT * G3;
    float xr = xgp[j], xz = xgp[HID + j], xn = xgp[2 * HID + j];
    float* op = hout + (size_t)b * TT * HID;

    __syncthreads();

    int p = 0;
    for (int t = 0; t < TT; t++) {
        // prefetch next step's xg (hides DRAM latency behind this matvec)
        float xr_n = 0.f, xz_n = 0.f, xn_n = 0.f;
        if (t + 1 < TT) {
            const float* xq = xgp + (t + 1) * G3;
            xr_n = xq[j]; xz_n = xq[HID + j]; xn_n = xq[2 * HID + j];
        }

        u64 ar = 0, az = 0, an = 0;
        const ulonglong2* hv = (const ulonglong2*)&hbuf[p][grp][half * 32];
#pragma unroll
        for (int q = 0; q < 8; q++) {
            ulonglong2 h2 = hv[q];                // LDS.128 broadcast
            ffma2(ar, wr[2 * q], h2.x); ffma2(ar, wr[2 * q + 1], h2.y);
            ffma2(az, wz[2 * q], h2.x); ffma2(az, wz[2 * q + 1], h2.y);
            ffma2(an, wn[2 * q], h2.x); ffma2(an, wn[2 * q + 1], h2.y);
        }
        float pr = hsum2(ar), pz = hsum2(az), pn = hsum2(an);
        pr += __shfl_xor_sync(0xffffffffu, pr, 1);
        pz += __shfl_xor_sync(0xffffffffu, pz, 1);
        pn += __shfl_xor_sync(0xffffffffu, pn, 1);

        float r  = fsig(xr + br + pr);
        float z  = fsig(xz + bz + pz);
        float n  = ftanh_fast(xn + r * (bn + pn));
        float hn = n + z * (hprev - n);
        hprev = hn;

        if (half == 0) {
            hbuf[p ^ 1][grp][j] = hn;
            if (WRITE_ALL)            op[t * HID + j] = hn;
            else if (t == TT - 1)     op[(TT - 1) * HID + j] = hn;
        }
        asm volatile("bar.sync %0, 128;" :: "r"(barid) : "memory");
        p ^= 1;
        xr = xr_n; xz = xz_n; xn = xn_n;
    }
}

// ---------------- final FC on last timestep -------------------------------
__global__ void fc_kernel(int insel, const float* __restrict__ wfc,
                          const float* __restrict__ bfc, float* __restrict__ out)
{
    const float* __restrict__ hin = insel ? g_hB : g_hA;
    int b = blockIdx.x;
    int j = threadIdx.x;                   // 64
    __shared__ float s[64];
    s[j] = hin[((size_t)b * TT + (TT - 1)) * HID + j] * wfc[j];
    __syncthreads();
    if (j < 32) {
        float a = s[j] + s[j + 32];
        for (int o = 16; o > 0; o >>= 1) a += __shfl_down_sync(0xffffffff, a, o);
        if (j == 0) out[b] = a + bfc[0];
    }
}

// ---------------- launch ---------------------------------------------------
extern "C" void kernel_launch(void* const* d_in, const int* in_sizes, int n_in,
                              void* d_out, int out_size)
{
    const float* x     = (const float*)d_in[0];
    const float* w_ih0 = (const float*)d_in[1];
    const float* w_hh0 = (const float*)d_in[2];
    const float* b_ih0 = (const float*)d_in[3];
    const float* b_hh0 = (const float*)d_in[4];
    const float* w_ih  = (const float*)d_in[5];
    const float* w_hh  = (const float*)d_in[6];
    const float* b_ih  = (const float*)d_in[7];
    const float* b_hh  = (const float*)d_in[8];
    const float* w_fc  = (const float*)d_in[9];
    const float* b_fc  = (const float*)d_in[10];
    float* out = (float*)d_out;

    // layer 0
    xg0_kernel<<<(BB * TT) / 8, 192>>>(x, w_ih0, b_ih0);
    rec_kernel<true><<<BB / 4, 512>>>(w_hh0, b_hh0, /*outsel=*/0);   // -> A

    // layers 1..4: xg GEMM then recurrence, ping-ponging A/B
    int insel = 0;
    for (int l = 0; l < 4; l++) {
        xg_gemm_kernel<<<(BB * TT) / GEMM_ROWS, 192>>>(
            insel, w_ih + (size_t)l * G3 * HID, b_ih + (size_t)l * G3);
        int outsel = insel ^ 1;
        if (l < 3)
            rec_kernel<true><<<BB / 4, 512>>>(
                w_hh + (size_t)l * G3 * HID, b_hh + (size_t)l * G3, outsel);
        else  // last layer: only t = TT-1 is consumed by fc
            rec_kernel<false><<<BB / 4, 512>>>(
                w_hh + (size_t)l * G3 * HID, b_hh + (size_t)l * G3, outsel);
        insel = outsel;
    }

    fc_kernel<<<BB, 64>>>(insel, w_fc, b_fc, out);
}

// round 6
// speedup vs baseline: 1.0127x; 1.0127x over previous
#include <cuda_runtime.h>

#define HID 64
#define G3  192     // 3*H
#define BB  512
#define TT  1024
#define GEMM_ROWS 128

// ---------------- scratch (device globals; no allocations) ----------------
__device__ float g_xg[(size_t)BB * TT * G3];   // 402 MB
__device__ float g_hA[(size_t)BB * TT * HID];  // 134 MB
__device__ float g_hB[(size_t)BB * TT * HID];  // 134 MB

typedef unsigned long long u64;

__device__ __forceinline__ void ffma2(u64& acc, u64 a, u64 b) {
    asm("fma.rn.f32x2 %0, %1, %2, %0;" : "+l"(acc) : "l"(a), "l"(b));
}
__device__ __forceinline__ float hsum2(u64 v) {
    float lo, hi;
    asm("mov.b64 {%0, %1}, %2;" : "=f"(lo), "=f"(hi) : "l"(v));
    return lo + hi;
}

// HW tanh (MUFU.TANH, sm_75+): lat ~16 vs ~50 for exp/div sequence
__device__ __forceinline__ float htanh(float x) {
    float y;
    asm("tanh.approx.f32 %0, %1;" : "=f"(y) : "f"(x));
    return y;
}
__device__ __forceinline__ float hsig(float x) {
    return fmaf(0.5f, htanh(0.5f * x), 0.5f);
}

// ---------------- layer-0 input pre-activations (K=5, memory bound) -------
__global__ __launch_bounds__(192) void xg0_kernel(
    const float* __restrict__ x, const float* __restrict__ w,
    const float* __restrict__ b)
{
    __shared__ float ws[G3 * 5];
    __shared__ float bs[G3];
    __shared__ float xs[8][5];
    int g = threadIdx.x;                  // 0..191
    for (int i = g; i < G3 * 5; i += 192) ws[i] = w[i];
    if (g < G3) bs[g] = b[g];
    size_t row0 = (size_t)blockIdx.x * 8;
    if (g < 40) xs[g / 5][g % 5] = x[row0 * 5 + g];
    __syncthreads();
#pragma unroll
    for (int r = 0; r < 8; r++) {
        float acc = bs[g];
#pragma unroll
        for (int i = 0; i < 5; i++) acc += xs[r][i] * ws[g * 5 + i];
        g_xg[(row0 + r) * G3 + g] = acc;
    }
}

// ---------------- xg GEMM for layers 1..4: [BT,64]x[64,192]+b -------------
// 2 output cols per thread (g, g+96), rows split in halves across warps.
__global__ void __launch_bounds__(192, 2) xg_gemm_kernel(
    int insel, const float* __restrict__ w, const float* __restrict__ bias)
{
    const float* __restrict__ hin = insel ? g_hB : g_hA;
    __shared__ __align__(16) float hs[GEMM_ROWS][HID];  // 32 KB
    int t  = threadIdx.x;
    int g  = t % 96;                      // column-pair base
    int rh = t / 96;                      // row half

    u64 w0[32], w1[32];
    const ulonglong2* p0 = (const ulonglong2*)&w[(size_t)g * HID];
    const ulonglong2* p1 = (const ulonglong2*)&w[(size_t)(g + 96) * HID];
#pragma unroll
    for (int q = 0; q < 16; q++) {
        ulonglong2 a = p0[q]; w0[2 * q] = a.x; w0[2 * q + 1] = a.y;
        ulonglong2 c = p1[q]; w1[2 * q] = c.x; w1[2 * q + 1] = c.y;
    }
    float b0 = bias[g], b1 = bias[g + 96];

    size_t row0 = (size_t)blockIdx.x * GEMM_ROWS;
    const float4* src = (const float4*)&hin[row0 * HID];
    float4* dst = (float4*)&hs[0][0];
    for (int i = t; i < GEMM_ROWS * HID / 4; i += 192) dst[i] = src[i];
    __syncthreads();

    float* outp = &g_xg[(row0 + (size_t)rh * 64) * G3];
#pragma unroll 1
    for (int r = 0; r < 64; r++) {
        u64 a0 = 0, a1 = 0, c0 = 0, c1 = 0;
        const ulonglong2* hrow = (const ulonglong2*)&hs[rh * 64 + r][0];
#pragma unroll
        for (int q = 0; q < 16; q++) {
            ulonglong2 hv = hrow[q];            // LDS.128 broadcast per warp
            ffma2(a0, w0[2 * q], hv.x);
            ffma2(a1, w0[2 * q + 1], hv.y);
            ffma2(c0, w1[2 * q], hv.x);
            ffma2(c1, w1[2 * q + 1], hv.y);
        }
        outp[r * G3 + g]      = b0 + hsum2(a0) + hsum2(a1);
        outp[r * G3 + g + 96] = b1 + hsum2(c0) + hsum2(c1);
    }
}

// ---------------- recurrence: 1 thread = 1 hidden unit, all 3 gates -------
// R3 mapping (measured best) + per-group skew to break SMSP convoying
// + MUFU tanh gates to shorten the serial gate chain.
template<bool WRITE_ALL>
__global__ void __launch_bounds__(256, 1) rec_kernel(
    const float* __restrict__ whh, const float* __restrict__ bhh, int outsel)
{
    float* __restrict__ hout = outsel ? g_hB : g_hA;
    __shared__ __align__(16) float hbuf[2][4][HID];   // double-buffered h

    int tid = threadIdx.x;
    int grp = tid >> 6;                   // 0..3 (batch row within CTA)
    int j   = tid & 63;                   // hidden unit
    int b   = blockIdx.x * 4 + grp;
    int barid = grp + 1;

    // weights: rows j (r), 64+j (z), 128+j (n), packed pairs in u64
    u64 wr[32], wz[32], wn[32];
    {
        const ulonglong2* rr = (const ulonglong2*)&whh[(size_t)j * HID];
        const ulonglong2* rz = (const ulonglong2*)&whh[(size_t)(HID + j) * HID];
        const ulonglong2* rn = (const ulonglong2*)&whh[(size_t)(2 * HID + j) * HID];
#pragma unroll
        for (int q = 0; q < 16; q++) {
            ulonglong2 a = rr[q]; wr[2 * q] = a.x; wr[2 * q + 1] = a.y;
            ulonglong2 c = rz[q]; wz[2 * q] = c.x; wz[2 * q + 1] = c.y;
            ulonglong2 d = rn[q]; wn[2 * q] = d.x; wn[2 * q + 1] = d.y;
        }
    }
    float br = bhh[j], bz = bhh[HID + j], bn = bhh[2 * HID + j];

    hbuf[0][grp][j] = 0.0f;
    float hprev = 0.0f;

    const float* xgp = &g_xg[(size_t)b * TT * G3];
    float xr = xgp[j], xz = xgp[HID + j], xn0 = xgp[2 * HID + j];

    // one-time per-group skew: dephase the two groups sharing each SMSP so
    // their per-step stalls interleave instead of convoying.
    {
        float skew = 0.0f;
        int iters = grp * 24;
#pragma unroll 1
        for (int i = 0; i < iters; i++)
            skew = fmaf(skew, 0.9999f, 1e-8f);
        if (skew == 1234.5678f) hout[0] = skew;  // never true; keeps chain
    }

    asm volatile("bar.sync %0, 64;" :: "r"(barid) : "memory");

    int p = 0;
    for (int t = 0; t < TT; t++) {
        // prefetch xg for t+1
        float xr_n = 0.f, xz_n = 0.f, xn_n = 0.f;
        if (t + 1 < TT) {
            const float* xq = xgp + (size_t)(t + 1) * G3;
            xr_n = xq[j]; xz_n = xq[HID + j]; xn_n = xq[2 * HID + j];
        }

        // gh matvec for all three gates (h broadcast from smem)
        u64 ar0 = 0, ar1 = 0, az0 = 0, az1 = 0, an0 = 0, an1 = 0;
        const ulonglong2* hrow = (const ulonglong2*)&hbuf[p][grp][0];
#pragma unroll
        for (int q = 0; q < 16; q++) {
            ulonglong2 hv = hrow[q];              // LDS.128 broadcast
            ffma2(ar0, wr[2 * q], hv.x);
            ffma2(ar1, wr[2 * q + 1], hv.y);
            ffma2(az0, wz[2 * q], hv.x);
            ffma2(az1, wz[2 * q + 1], hv.y);
            ffma2(an0, wn[2 * q], hv.x);
            ffma2(an1, wn[2 * q + 1], hv.y);
        }
        float ghr = br + hsum2(ar0) + hsum2(ar1);
        float ghz = bz + hsum2(az0) + hsum2(az1);
        float ghn = bn + hsum2(an0) + hsum2(an1);

        float r  = hsig(xr + ghr);
        float z  = hsig(xz + ghz);
        float n  = htanh(xn0 + r * ghn);
        float hn = n + z * (hprev - n);

        hbuf[p ^ 1][grp][j] = hn;
        hprev = hn;
        if (WRITE_ALL || t == TT - 1)
            hout[((size_t)b * TT + t) * HID + j] = hn;

        asm volatile("bar.sync %0, 64;" :: "r"(barid) : "memory");
        p ^= 1;
        xr = xr_n; xz = xz_n; xn0 = xn_n;
    }
}

// ---------------- final FC on last timestep -------------------------------
__global__ void fc_kernel(int insel, const float* __restrict__ wfc,
                          const float* __restrict__ bfc, float* __restrict__ out)
{
    const float* __restrict__ hin = insel ? g_hB : g_hA;
    int b = blockIdx.x;
    int j = threadIdx.x;                   // 64
    __shared__ float s[64];
    s[j] = hin[((size_t)b * TT + (TT - 1)) * HID + j] * wfc[j];
    __syncthreads();
    if (j < 32) {
        float a = s[j] + s[j + 32];
        for (int o = 16; o > 0; o >>= 1) a += __shfl_down_sync(0xffffffff, a, o);
        if (j == 0) out[b] = a + bfc[0];
    }
}

// ---------------- launch ---------------------------------------------------
extern "C" void kernel_launch(void* const* d_in, const int* in_sizes, int n_in,
                              void* d_out, int out_size)
{
    const float* x     = (const float*)d_in[0];
    const float* w_ih0 = (const float*)d_in[1];
    const float* w_hh0 = (const float*)d_in[2];
    const float* b_ih0 = (const float*)d_in[3];
    const float* b_hh0 = (const float*)d_in[4];
    const float* w_ih  = (const float*)d_in[5];
    const float* w_hh  = (const float*)d_in[6];
    const float* b_ih  = (const float*)d_in[7];
    const float* b_hh  = (const float*)d_in[8];
    const float* w_fc  = (const float*)d_in[9];
    const float* b_fc  = (const float*)d_in[10];
    float* out = (float*)d_out;

    // layer 0
    xg0_kernel<<<(BB * TT) / 8, 192>>>(x, w_ih0, b_ih0);
    rec_kernel<true><<<BB / 4, 256>>>(w_hh0, b_hh0, /*outsel=*/0);   // -> A

    // layers 1..4: xg GEMM then recurrence, ping-ponging A/B
    int insel = 0;
    for (int l = 0; l < 4; l++) {
        xg_gemm_kernel<<<(BB * TT) / GEMM_ROWS, 192>>>(
            insel, w_ih + (size_t)l * G3 * HID, b_ih + (size_t)l * G3);
        int outsel = insel ^ 1;
        if (l < 3)
            rec_kernel<true><<<BB / 4, 256>>>(
                w_hh + (size_t)l * G3 * HID, b_hh + (size_t)l * G3, outsel);
        else  // last layer: only t = TT-1 is consumed by fc
            rec_kernel<false><<<BB / 4, 256>>>(
                w_hh + (size_t)l * G3 * HID, b_hh + (size_t)l * G3, outsel);
        insel = outsel;
    }

    fc_kernel<<<BB, 64>>>(insel, w_fc, b_fc, out);
}